// round 1
// baseline (speedup 1.0000x reference)
#include <cuda_runtime.h>
#include <math.h>

// Problem constants (fixed by the reference)
#define BB 64
#define TT 512
#define FF 513
#define HH 50
#define G4 200          // 4*H
#define MROWS (BB*TT)   // 32768

// Scratch (static device globals — no allocation in kernel_launch)
__device__ float g_xg[MROWS * G4];   // (B*T, 200): xg = x@W_ih^T + b_ih
__device__ float g_hs[MROWS * HH];   // (B*T, 50):  hidden states

// ---------------------------------------------------------------------------
// Generic NT sgemm with bias: C[m,n] = sum_k A[m,k]*Bm[n,k] + bias[n]
// BM=128, BN=64, BK=16, 256 threads, 8x4 register tile per thread.
// M must be a multiple of 128 (true here: 32768). N,K arbitrary (guarded).
// ---------------------------------------------------------------------------
#define BM 128
#define BN 64
#define BKK 16
#define TM 8
#define TN 4

__global__ __launch_bounds__(256) void gemm_nt_bias(
    const float* __restrict__ A, const float* __restrict__ Bm,
    const float* __restrict__ bias, float* __restrict__ C,
    int M, int N, int K)
{
    __shared__ float As[BKK][BM + 4];   // padded: 132
    __shared__ float Bs[BKK][BN + 4];   // padded: 68

    const int tid = threadIdx.x;
    const int tx = tid & 15;   // N dim (16)
    const int ty = tid >> 4;   // M dim (16)

    const int m0 = blockIdx.x * BM;
    const int n0 = blockIdx.y * BN;

    float acc[TM][TN];
#pragma unroll
    for (int i = 0; i < TM; ++i)
#pragma unroll
        for (int j = 0; j < TN; ++j) acc[i][j] = 0.f;

    const int nKT = (K + BKK - 1) / BKK;
    for (int kt = 0; kt < nKT; ++kt) {
        const int k0 = kt * BKK;

        // Load A tile (128x16), 8 elems/thread, k-fastest for coalescing
#pragma unroll
        for (int i = 0; i < (BM * BKK) / 256; ++i) {
            int idx = tid + i * 256;
            int r = idx >> 4;        // 0..127
            int k = idx & 15;
            int gk = k0 + k;
            As[k][r] = (gk < K) ? A[(size_t)(m0 + r) * K + gk] : 0.f;
        }
        // Load B tile (64x16), 4 elems/thread
#pragma unroll
        for (int i = 0; i < (BN * BKK) / 256; ++i) {
            int idx = tid + i * 256;
            int r = idx >> 4;        // 0..63
            int k = idx & 15;
            int gk = k0 + k;
            int gn = n0 + r;
            Bs[k][r] = (gk < K && gn < N) ? Bm[(size_t)gn * K + gk] : 0.f;
        }
        __syncthreads();

#pragma unroll
        for (int kk = 0; kk < BKK; ++kk) {
            float4 a0 = *(const float4*)&As[kk][ty * TM];
            float4 a1 = *(const float4*)&As[kk][ty * TM + 4];
            float4 b0 = *(const float4*)&Bs[kk][tx * TN];
            float av[TM] = {a0.x, a0.y, a0.z, a0.w, a1.x, a1.y, a1.z, a1.w};
            float bv[TN] = {b0.x, b0.y, b0.z, b0.w};
#pragma unroll
            for (int i = 0; i < TM; ++i)
#pragma unroll
                for (int j = 0; j < TN; ++j)
                    acc[i][j] += av[i] * bv[j];
        }
        __syncthreads();
    }

    // Epilogue
#pragma unroll
    for (int j = 0; j < TN; ++j) {
        int col = n0 + tx * TN + j;
        if (col < N) {
            float bb = bias[col];
#pragma unroll
            for (int i = 0; i < TM; ++i) {
                int row = m0 + ty * TM + i;
                C[(size_t)row * N + col] = acc[i][j] + bb;
            }
        }
    }
}

// ---------------------------------------------------------------------------
// LSTM scan over batch axis. One block per t (grid 512, 256 threads).
// Thread j < 200 owns gate row j: W_hh[j][0..49] lives in registers.
// Threads j < 50 own unit j: keep c_j in a register, update h in smem.
// ---------------------------------------------------------------------------
__global__ __launch_bounds__(256) void lstm_scan(
    const float* __restrict__ W_hh, const float* __restrict__ b_hh)
{
    __shared__ float h_s[HH];
    __shared__ float g_s[G4];

    const int t = blockIdx.x;
    const int j = threadIdx.x;

    float w[HH];
    float bj = 0.f;
    if (j < G4) {
#pragma unroll
        for (int k = 0; k < HH; ++k) w[k] = W_hh[j * HH + k];
        bj = b_hh[j];
    }
    float c = 0.f;
    if (j < HH) h_s[j] = 0.f;
    __syncthreads();

    for (int b = 0; b < BB; ++b) {
        if (j < G4) {
            float g0 = g_xg[((size_t)b * TT + t) * G4 + j] + bj;
            float g1 = 0.f, g2 = 0.f, g3 = 0.f;
            // 4 partial accumulators to break the FFMA dependency chain
#pragma unroll
            for (int k = 0; k < 48; k += 4) {
                g0 += w[k + 0] * h_s[k + 0];
                g1 += w[k + 1] * h_s[k + 1];
                g2 += w[k + 2] * h_s[k + 2];
                g3 += w[k + 3] * h_s[k + 3];
            }
            g0 += w[48] * h_s[48];
            g1 += w[49] * h_s[49];
            g_s[j] = (g0 + g1) + (g2 + g3);
        }
        __syncthreads();
        if (j < HH) {
            float gi = g_s[j];
            float gf = g_s[j + HH];
            float gg = g_s[j + 2 * HH];
            float go = g_s[j + 3 * HH];
            float si = 1.f / (1.f + expf(-gi));
            float sf = 1.f / (1.f + expf(-gf));
            float so = 1.f / (1.f + expf(-go));
            float tg = tanhf(gg);
            c = sf * c + si * tg;
            float hv = so * tanhf(c);
            h_s[j] = hv;
            g_hs[((size_t)b * TT + t) * HH + j] = hv;
        }
        __syncthreads();
    }
}

// ---------------------------------------------------------------------------
extern "C" void kernel_launch(void* const* d_in, const int* in_sizes, int n_in,
                              void* d_out, int out_size)
{
    const float* x     = (const float*)d_in[0];  // (B,T,F)
    const float* W_ih  = (const float*)d_in[1];  // (200,513)
    const float* W_hh  = (const float*)d_in[2];  // (200,50)
    const float* b_ih  = (const float*)d_in[3];  // (200,)
    const float* b_hh  = (const float*)d_in[4];  // (200,)
    const float* W_out = (const float*)d_in[5];  // (513,50)
    const float* b_out = (const float*)d_in[6];  // (513,)
    float* out = (float*)d_out;                  // (B,T,F)

    float* xg = nullptr;
    float* hs = nullptr;
    cudaGetSymbolAddress((void**)&xg, g_xg);
    cudaGetSymbolAddress((void**)&hs, g_hs);

    // 1) xg = x @ W_ih^T + b_ih   (M=32768, N=200, K=513)
    {
        dim3 grid(MROWS / BM, (G4 + BN - 1) / BN);
        gemm_nt_bias<<<grid, 256>>>(x, W_ih, b_ih, xg, MROWS, G4, FF);
    }
    // 2) LSTM scan over batch axis (512 independent chains)
    lstm_scan<<<TT, 256>>>(W_hh, b_hh);

    // 3) out = hs @ W_out^T + b_out  (M=32768, N=513, K=50)
    {
        dim3 grid(MROWS / BM, (FF + BN - 1) / BN);
        gemm_nt_bias<<<grid, 256>>>(hs, W_out, b_out, out, MROWS, FF, HH);
    }
}

// round 2
// speedup vs baseline: 1.2806x; 1.2806x over previous
#include <cuda_runtime.h>
#include <math.h>

// Problem constants (fixed by the reference)
#define BB 64
#define TT 512
#define FF 513
#define HH 50
#define G4 200          // 4*H
#define MROWS (BB*TT)   // 32768

// Scratch (static device globals — no allocation in kernel_launch)
__device__ float g_xg[MROWS * G4];   // (B*T, 200): xg = x@W_ih^T + b_ih
__device__ float g_hs[MROWS * HH];   // (B*T, 50):  hidden states

// ---------------------------------------------------------------------------
// NT sgemm with bias: C[m,n] = sum_k A[m,k]*Bm[n,k] + bias[n]
// BM=128, BN=128, BK=16, 256 threads.
// Thread (tx=tid%32, ty=tid/32): owns rows ty*16..+15 (contiguous),
// cols tx+32*j, j<4 (interleaved) -> coalesced epilogue stores.
// Double-buffered smem. M must be a multiple of 128 (true: 32768).
// ---------------------------------------------------------------------------
#define BM 128
#define BN 128
#define BK 16
#define TM 16
#define TN 4
#define PAD 4

__global__ __launch_bounds__(256, 2) void gemm_nt_bias(
    const float* __restrict__ A, const float* __restrict__ Bm,
    const float* __restrict__ bias, float* __restrict__ C,
    int M, int N, int K)
{
    __shared__ float As[2][BK][BM + PAD];
    __shared__ float Bs[2][BK][BN + PAD];

    const int tid = threadIdx.x;
    const int tx = tid & 31;    // N lane
    const int ty = tid >> 5;    // M group (0..7), warp-uniform

    const int m0 = blockIdx.x * BM;
    const int n0 = blockIdx.y * BN;

    // load indexing: 256 threads, k fastest (coalesced 64B runs)
    const int lk = tid & 15;    // 0..15
    const int lr = tid >> 4;    // 0..15 row base; 8 passes of 16 rows

    float acc[TM][TN];
#pragma unroll
    for (int i = 0; i < TM; ++i)
#pragma unroll
        for (int j = 0; j < TN; ++j) acc[i][j] = 0.f;

    const int nKT = (K + BK - 1) / BK;

    float ra[8], rb[8];

    // ---- prologue: load tile 0 straight to smem buf 0
    {
        const int gk = lk;
        const bool kok = (gk < K);
#pragma unroll
        for (int i = 0; i < 8; ++i) {
            int r = lr + i * 16;
            As[0][lk][r] = kok ? A[(size_t)(m0 + r) * K + gk] : 0.f;
            int gn = n0 + r;
            Bs[0][lk][r] = (kok && gn < N) ? Bm[(size_t)gn * K + gk] : 0.f;
        }
    }
    __syncthreads();

    for (int kt = 0; kt < nKT; ++kt) {
        const int cur = kt & 1;
        const bool has_next = (kt + 1 < nKT);

        // ---- g2r prefetch of next tile
        if (has_next) {
            const int gk = (kt + 1) * BK + lk;
            const bool kok = (gk < K);
#pragma unroll
            for (int i = 0; i < 8; ++i) {
                int r = lr + i * 16;
                ra[i] = kok ? A[(size_t)(m0 + r) * K + gk] : 0.f;
                int gn = n0 + r;
                rb[i] = (kok && gn < N) ? Bm[(size_t)gn * K + gk] : 0.f;
            }
        }

        // ---- compute current tile
#pragma unroll
        for (int kk = 0; kk < BK; ++kk) {
            // A fragment: warp-uniform -> smem broadcast (free)
            float4 a0 = *(const float4*)&As[cur][kk][ty * TM + 0];
            float4 a1 = *(const float4*)&As[cur][kk][ty * TM + 4];
            float4 a2 = *(const float4*)&As[cur][kk][ty * TM + 8];
            float4 a3 = *(const float4*)&As[cur][kk][ty * TM + 12];
            float av[TM] = {a0.x, a0.y, a0.z, a0.w, a1.x, a1.y, a1.z, a1.w,
                            a2.x, a2.y, a2.z, a2.w, a3.x, a3.y, a3.z, a3.w};
            float bv[TN];
#pragma unroll
            for (int j = 0; j < TN; ++j) bv[j] = Bs[cur][kk][tx + 32 * j];
#pragma unroll
            for (int i = 0; i < TM; ++i)
#pragma unroll
                for (int j = 0; j < TN; ++j)
                    acc[i][j] += av[i] * bv[j];
        }

        // ---- r2s into alternate buffer
        if (has_next) {
            const int nxt = cur ^ 1;
#pragma unroll
            for (int i = 0; i < 8; ++i) {
                int r = lr + i * 16;
                As[nxt][lk][r] = ra[i];
                Bs[nxt][lk][r] = rb[i];
            }
            __syncthreads();
        }
    }

    // ---- epilogue: coalesced stores (col = n0 + tx + 32j)
#pragma unroll
    for (int j = 0; j < TN; ++j) {
        int col = n0 + tx + 32 * j;
        if (col < N) {
            float bb = bias[col];
#pragma unroll
            for (int i = 0; i < TM; ++i) {
                int row = m0 + ty * TM + i;
                C[(size_t)row * N + col] = acc[i][j] + bb;
            }
        }
    }
}

// ---------------------------------------------------------------------------
// LSTM scan over batch axis. One block per t (grid 512, 256 threads).
// Thread j < 200 owns gate row j: W_hh[j][0..49] lives in registers.
// Threads j < 50 own unit j: keep c_j in a register, update h in smem.
// ---------------------------------------------------------------------------
__global__ __launch_bounds__(256) void lstm_scan(
    const float* __restrict__ W_hh, const float* __restrict__ b_hh)
{
    __shared__ float h_s[HH];
    __shared__ float g_s[G4];

    const int t = blockIdx.x;
    const int j = threadIdx.x;

    float w[HH];
    float bj = 0.f;
    if (j < G4) {
#pragma unroll
        for (int k = 0; k < HH; ++k) w[k] = W_hh[j * HH + k];
        bj = b_hh[j];
    }
    float c = 0.f;
    if (j < HH) h_s[j] = 0.f;
    __syncthreads();

    for (int b = 0; b < BB; ++b) {
        if (j < G4) {
            float g0 = g_xg[((size_t)b * TT + t) * G4 + j] + bj;
            float g1 = 0.f, g2 = 0.f, g3 = 0.f;
#pragma unroll
            for (int k = 0; k < 48; k += 4) {
                g0 += w[k + 0] * h_s[k + 0];
                g1 += w[k + 1] * h_s[k + 1];
                g2 += w[k + 2] * h_s[k + 2];
                g3 += w[k + 3] * h_s[k + 3];
            }
            g0 += w[48] * h_s[48];
            g1 += w[49] * h_s[49];
            g_s[j] = (g0 + g1) + (g2 + g3);
        }
        __syncthreads();
        if (j < HH) {
            float gi = g_s[j];
            float gf = g_s[j + HH];
            float gg = g_s[j + 2 * HH];
            float go = g_s[j + 3 * HH];
            float si = 1.f / (1.f + expf(-gi));
            float sf = 1.f / (1.f + expf(-gf));
            float so = 1.f / (1.f + expf(-go));
            float tg = tanhf(gg);
            c = sf * c + si * tg;
            float hv = so * tanhf(c);
            h_s[j] = hv;
            g_hs[((size_t)b * TT + t) * HH + j] = hv;
        }
        __syncthreads();
    }
}

// ---------------------------------------------------------------------------
extern "C" void kernel_launch(void* const* d_in, const int* in_sizes, int n_in,
                              void* d_out, int out_size)
{
    const float* x     = (const float*)d_in[0];  // (B,T,F)
    const float* W_ih  = (const float*)d_in[1];  // (200,513)
    const float* W_hh  = (const float*)d_in[2];  // (200,50)
    const float* b_ih  = (const float*)d_in[3];  // (200,)
    const float* b_hh  = (const float*)d_in[4];  // (200,)
    const float* W_out = (const float*)d_in[5];  // (513,50)
    const float* b_out = (const float*)d_in[6];  // (513,)
    float* out = (float*)d_out;                  // (B,T,F)

    float* xg = nullptr;
    float* hs = nullptr;
    cudaGetSymbolAddress((void**)&xg, g_xg);
    cudaGetSymbolAddress((void**)&hs, g_hs);

    // 1) xg = x @ W_ih^T + b_ih   (M=32768, N=200, K=513)
    {
        dim3 grid(MROWS / BM, (G4 + BN - 1) / BN);
        gemm_nt_bias<<<grid, 256>>>(x, W_ih, b_ih, xg, MROWS, G4, FF);
    }
    // 2) LSTM scan over batch axis (512 independent chains)
    lstm_scan<<<TT, 256>>>(W_hh, b_hh);

    // 3) out = hs @ W_out^T + b_out  (M=32768, N=513, K=50)
    {
        dim3 grid(MROWS / BM, (FF + BN - 1) / BN);
        gemm_nt_bias<<<grid, 256>>>(hs, W_out, b_out, out, MROWS, FF, HH);
    }
}

// round 4
// speedup vs baseline: 1.8964x; 1.4810x over previous
#include <cuda_runtime.h>
#include <cuda_bf16.h>
#include <math.h>
#include <stdint.h>

// Problem constants (fixed by the reference)
#define BB 64
#define TT 512
#define FF 513
#define HH 50
#define G4 200          // 4*H
#define MROWS (BB*TT)   // 32768

// Scratch (static device globals — no allocation in kernel_launch)
__device__ float g_xg[MROWS * G4];   // (B*T, 200): xg = x@W_ih^T + b_ih
__device__ float g_hs[MROWS * HH];   // (B*T, 50):  hidden states

// ===========================================================================
// Warp-MMA helpers (sm_80-era PTX: compiles at compute_103, runs on tensor pipe)
// ===========================================================================
__device__ __forceinline__ uint32_t smem_u32(const void* p) {
    uint32_t a;
    asm("{ .reg .u64 t; cvta.to.shared.u64 t, %1; cvt.u32.u64 %0, t; }"
        : "=r"(a) : "l"(p));
    return a;
}

__device__ __forceinline__ void ldsm4(uint32_t* r, uint32_t a) {
    asm volatile("ldmatrix.sync.aligned.m8n8.x4.shared.b16 {%0,%1,%2,%3}, [%4];"
                 : "=r"(r[0]), "=r"(r[1]), "=r"(r[2]), "=r"(r[3]) : "r"(a));
}

__device__ __forceinline__ void mma16816(float* c, const uint32_t* a,
                                         const uint32_t* b) {
    asm volatile(
        "mma.sync.aligned.m16n8k16.row.col.f32.bf16.bf16.f32 "
        "{%0,%1,%2,%3}, {%4,%5,%6,%7}, {%8,%9}, {%0,%1,%2,%3};"
        : "+f"(c[0]), "+f"(c[1]), "+f"(c[2]), "+f"(c[3])
        : "r"(a[0]), "r"(a[1]), "r"(a[2]), "r"(a[3]), "r"(b[0]), "r"(b[1]));
}

// ===========================================================================
// NT GEMM with bias on tensor cores via fp32 -> bf16 hi/lo split.
//   C[m,n] = sum_k A[m,k] * B[n,k] + bias[n]
// Block tile 128x128, K chunk 32. 8 warps: 2(m) x 4(n); warp tile 64x32.
// smem rows padded to 40 bf16 (80 B) -> conflict-free ldmatrix.
// M must be a multiple of 128 (true: 32768). N, K arbitrary (guarded).
// ===========================================================================
#define LDR 40   // smem row stride in bf16 elements (80 bytes)

__global__ __launch_bounds__(256) void gemm_mma_nt(
    const float* __restrict__ A, const float* __restrict__ Bm,
    const float* __restrict__ bias, float* __restrict__ C,
    int M, int N, int K)
{
    __shared__ __align__(16) __nv_bfloat16 sA[2][128 * LDR];  // [hi/lo]
    __shared__ __align__(16) __nv_bfloat16 sB[2][128 * LDR];

    const int tid  = threadIdx.x;
    const int lane = tid & 31;
    const int wid  = tid >> 5;
    const int wm   = wid & 1;    // 0..1 -> m offset 0/64
    const int wn   = wid >> 1;   // 0..3 -> n offset 0/32/64/96

    const int m0 = blockIdx.x * 128;
    const int n0 = blockIdx.y * 128;

    float acc[4][4][4];
#pragma unroll
    for (int i = 0; i < 4; ++i)
#pragma unroll
        for (int j = 0; j < 4; ++j)
#pragma unroll
            for (int q = 0; q < 4; ++q) acc[i][j][q] = 0.f;

    // loader indexing: thread handles col pair (lc, lc+1), rows lr + 16*i
    const int lc = (tid & 15) * 2;
    const int lr = tid >> 4;

    const uint32_t sAhi = smem_u32(&sA[0][0]);
    const uint32_t sAlo = smem_u32(&sA[1][0]);
    const uint32_t sBhi = smem_u32(&sB[0][0]);
    const uint32_t sBlo = smem_u32(&sB[1][0]);

    const int nKC = (K + 31) / 32;

    for (int kc = 0; kc < nKC; ++kc) {
        const int gk = kc * 32 + lc;
        const bool k0ok = (gk < K);
        const bool k1ok = (gk + 1 < K);

        // ---- load + convert A (128x32) and B (128x32) chunks
#pragma unroll
        for (int i = 0; i < 8; ++i) {
            const int row = lr + i * 16;

            float a0 = k0ok ? A[(size_t)(m0 + row) * K + gk] : 0.f;
            float a1 = k1ok ? A[(size_t)(m0 + row) * K + gk + 1] : 0.f;
            __nv_bfloat16 ah0 = __float2bfloat16(a0);
            __nv_bfloat16 ah1 = __float2bfloat16(a1);
            __nv_bfloat16 al0 = __float2bfloat16(a0 - __bfloat162float(ah0));
            __nv_bfloat16 al1 = __float2bfloat16(a1 - __bfloat162float(ah1));
            *(__nv_bfloat162*)&sA[0][row * LDR + lc] = __nv_bfloat162(ah0, ah1);
            *(__nv_bfloat162*)&sA[1][row * LDR + lc] = __nv_bfloat162(al0, al1);

            const int gn = n0 + row;
            const bool nok = (gn < N);
            float b0 = (k0ok && nok) ? Bm[(size_t)gn * K + gk] : 0.f;
            float b1 = (k1ok && nok) ? Bm[(size_t)gn * K + gk + 1] : 0.f;
            __nv_bfloat16 bh0 = __float2bfloat16(b0);
            __nv_bfloat16 bh1 = __float2bfloat16(b1);
            __nv_bfloat16 bl0 = __float2bfloat16(b0 - __bfloat162float(bh0));
            __nv_bfloat16 bl1 = __float2bfloat16(b1 - __bfloat162float(bh1));
            *(__nv_bfloat162*)&sB[0][row * LDR + lc] = __nv_bfloat162(bh0, bh1);
            *(__nv_bfloat162*)&sB[1][row * LDR + lc] = __nv_bfloat162(bl0, bl1);
        }
        __syncthreads();

        // ---- compute: 2 k16 steps
#pragma unroll
        for (int k16 = 0; k16 < 2; ++k16) {
            const uint32_t kb = k16 * 32;  // 16 bf16 = 32 bytes

            // A fragments: 4 m16 tiles, hi and lo
            uint32_t ah[4][4], al[4][4];
#pragma unroll
            for (int mi = 0; mi < 4; ++mi) {
                const uint32_t rowb =
                    (uint32_t)(wm * 64 + mi * 16 + (lane & 15)) * (LDR * 2);
                const uint32_t off = rowb + ((lane >> 4) * 16) + kb;
                ldsm4(ah[mi], sAhi + off);
                ldsm4(al[mi], sAlo + off);
            }
            // B fragments: 4 n8 tiles via 2 x4 loads, hi and lo
            uint32_t bh[4][2], bl[4][2];
#pragma unroll
            for (int jj = 0; jj < 2; ++jj) {
                const uint32_t nrow =
                    (uint32_t)(wn * 32 + jj * 16 + ((lane >> 4) & 1) * 8 +
                               (lane & 7));
                const uint32_t off =
                    nrow * (LDR * 2) + (((lane >> 3) & 1) * 16) + kb;
                uint32_t t[4];
                ldsm4(t, sBhi + off);
                bh[jj * 2][0] = t[0]; bh[jj * 2][1] = t[1];
                bh[jj * 2 + 1][0] = t[2]; bh[jj * 2 + 1][1] = t[3];
                ldsm4(t, sBlo + off);
                bl[jj * 2][0] = t[0]; bl[jj * 2][1] = t[1];
                bl[jj * 2 + 1][0] = t[2]; bl[jj * 2 + 1][1] = t[3];
            }
            // 3-product split accumulate
#pragma unroll
            for (int mi = 0; mi < 4; ++mi)
#pragma unroll
                for (int nj = 0; nj < 4; ++nj) {
                    mma16816(acc[mi][nj], ah[mi], bh[nj]);
                    mma16816(acc[mi][nj], ah[mi], bl[nj]);
                    mma16816(acc[mi][nj], al[mi], bh[nj]);
                }
        }
        __syncthreads();
    }

    // ---- epilogue: fragment layout c0,c1 = (row, 2c..2c+1), c2,c3 = row+8
    const int rbase = m0 + wm * 64 + (lane >> 2);
    const int cbase = n0 + wn * 32 + (lane & 3) * 2;
#pragma unroll
    for (int mi = 0; mi < 4; ++mi) {
#pragma unroll
        for (int nj = 0; nj < 4; ++nj) {
            const int col = cbase + nj * 8;
            const int row = rbase + mi * 16;
            if (col < N) {
                const float bb0 = bias[col];
                C[(size_t)row * N + col] = acc[mi][nj][0] + bb0;
                C[(size_t)(row + 8) * N + col] = acc[mi][nj][2] + bb0;
            }
            if (col + 1 < N) {
                const float bb1 = bias[col + 1];
                C[(size_t)row * N + col + 1] = acc[mi][nj][1] + bb1;
                C[(size_t)(row + 8) * N + col + 1] = acc[mi][nj][3] + bb1;
            }
        }
    }
}

// ---------------------------------------------------------------------------
// LSTM scan over batch axis. One block per t (grid 512, 256 threads).
// ---------------------------------------------------------------------------
__global__ __launch_bounds__(256) void lstm_scan(
    const float* __restrict__ W_hh, const float* __restrict__ b_hh)
{
    __shared__ float h_s[HH];
    __shared__ float g_s[G4];

    const int t = blockIdx.x;
    const int j = threadIdx.x;

    float w[HH];
    float bj = 0.f;
    if (j < G4) {
#pragma unroll
        for (int k = 0; k < HH; ++k) w[k] = W_hh[j * HH + k];
        bj = b_hh[j];
    }
    float c = 0.f;
    if (j < HH) h_s[j] = 0.f;
    __syncthreads();

    for (int b = 0; b < BB; ++b) {
        if (j < G4) {
            float g0 = g_xg[((size_t)b * TT + t) * G4 + j] + bj;
            float g1 = 0.f, g2 = 0.f, g3 = 0.f;
#pragma unroll
            for (int k = 0; k < 48; k += 4) {
                g0 += w[k + 0] * h_s[k + 0];
                g1 += w[k + 1] * h_s[k + 1];
                g2 += w[k + 2] * h_s[k + 2];
                g3 += w[k + 3] * h_s[k + 3];
            }
            g0 += w[48] * h_s[48];
            g1 += w[49] * h_s[49];
            g_s[j] = (g0 + g1) + (g2 + g3);
        }
        __syncthreads();
        if (j < HH) {
            float gi = g_s[j];
            float gf = g_s[j + HH];
            float gg = g_s[j + 2 * HH];
            float go = g_s[j + 3 * HH];
            float si = 1.f / (1.f + expf(-gi));
            float sf = 1.f / (1.f + expf(-gf));
            float so = 1.f / (1.f + expf(-go));
            float tg = tanhf(gg);
            c = sf * c + si * tg;
            float hv = so * tanhf(c);
            h_s[j] = hv;
            g_hs[((size_t)b * TT + t) * HH + j] = hv;
        }
        __syncthreads();
    }
}

// ---------------------------------------------------------------------------
extern "C" void kernel_launch(void* const* d_in, const int* in_sizes, int n_in,
                              void* d_out, int out_size)
{
    const float* x     = (const float*)d_in[0];  // (B,T,F)
    const float* W_ih  = (const float*)d_in[1];  // (200,513)
    const float* W_hh  = (const float*)d_in[2];  // (200,50)
    const float* b_ih  = (const float*)d_in[3];  // (200,)
    const float* b_hh  = (const float*)d_in[4];  // (200,)
    const float* W_out = (const float*)d_in[5];  // (513,50)
    const float* b_out = (const float*)d_in[6];  // (513,)
    float* out = (float*)d_out;                  // (B,T,F)

    float* xg = nullptr;
    float* hs = nullptr;
    cudaGetSymbolAddress((void**)&xg, g_xg);
    cudaGetSymbolAddress((void**)&hs, g_hs);

    // 1) xg = x @ W_ih^T + b_ih   (M=32768, N=200, K=513) — tensor cores
    {
        dim3 grid(MROWS / 128, (G4 + 127) / 128);   // (256, 2)
        gemm_mma_nt<<<grid, 256>>>(x, W_ih, b_ih, xg, MROWS, G4, FF);
    }
    // 2) LSTM scan over batch axis (512 independent chains)
    lstm_scan<<<TT, 256>>>(W_hh, b_hh);

    // 3) out = hs @ W_out^T + b_out  (M=32768, N=513, K=50) — tensor cores
    {
        dim3 grid(MROWS / 128, (FF + 127) / 128);   // (256, 5)
        gemm_mma_nt<<<grid, 256>>>(hs, W_out, b_out, out, MROWS, FF, HH);
    }
}